// round 2
// baseline (speedup 1.0000x reference)
#include <cuda_runtime.h>
#include <cstdint>
#include <cstddef>

// Problem constants
#define NB 2
#define LQ 2048
#define SK 2048
#define NH 16
#define EE 64
#define DD 64
#define GR 1024          // row stride in elements for Q/K/V/O: H*E = H*D = 1024

// Tile config
#define BM 128           // q rows per CTA
#define BN 64            // kv rows per tile
#define NTHREADS 256     // 8 warps, each owns 16 q rows

// SMEM row strides (floats)
#define QS 68            // Q staging / mask+P buffer stride (bank-shift 4)
#define KSS 68           // K tile stride
#define VSS 72           // V tile stride (bank-shift 8 -> conflict-free PV B loads)

#define SMEM_FLOATS (BM*QS + BN*KSS + BN*VSS)   // 8704+4352+4608 = 17664
#define SMEM_BYTES  (SMEM_FLOATS * 4)           // 70656 B

__device__ __forceinline__ float tf32_rna(float x) {
    uint32_t u;
    asm("cvt.rna.tf32.f32 %0, %1;" : "=r"(u) : "f"(x));
    return __uint_as_float(u);
}

// D += A * B, m16n8k8 tf32, A row-major (m x k), B "col" (element (k,n))
__device__ __forceinline__ void mma_tf32(float c[4], const float a[4], const float b[2]) {
    asm volatile(
        "mma.sync.aligned.m16n8k8.row.col.f32.tf32.tf32.f32 "
        "{%0,%1,%2,%3}, {%4,%5,%6,%7}, {%8,%9}, {%0,%1,%2,%3};"
        : "+f"(c[0]), "+f"(c[1]), "+f"(c[2]), "+f"(c[3])
        : "r"(__float_as_uint(a[0])), "r"(__float_as_uint(a[1])),
          "r"(__float_as_uint(a[2])), "r"(__float_as_uint(a[3])),
          "r"(__float_as_uint(b[0])), "r"(__float_as_uint(b[1])));
}

__global__ void __launch_bounds__(NTHREADS, 2)
attn_kernel(const float* __restrict__ q,
            const float* __restrict__ k,
            const float* __restrict__ v,
            const float* __restrict__ mask,
            float* __restrict__ out)
{
    extern __shared__ float smem[];
    float* Qsm = smem;                 // [BM][QS] : Q staging, then aliased as mask/P
    float* Ksm = smem + BM * QS;       // [BN][KSS]
    float* Vsm = Ksm + BN * KSS;       // [BN][VSS]
    float* MPs = Qsm;                  // alias: per-iter mask tile, then P tile

    const int tid  = threadIdx.x;
    const int w    = tid >> 5;         // warp 0..7 -> q rows [16w, 16w+16)
    const int lane = tid & 31;
    const int g    = lane >> 2;        // groupID 0..7
    const int tg   = lane & 3;         // thread-in-group 0..3

    const int q0 = blockIdx.x * BM;    // q tile start
    const int h  = blockIdx.y;
    const int b  = blockIdx.z;

    const float* qp = q    + (((size_t)b * LQ + q0) * NH + h) * EE;
    const float* kp = k    + (((size_t)b * SK) * NH + h) * EE;
    const float* vp = v    + (((size_t)b * SK) * NH + h) * DD;
    const float* mp = mask + (size_t)q0 * SK;
    float*       op = out  + (((size_t)b * LQ + q0) * NH + h) * DD;

    // ---- stage Q (fp32 -> tf32) ----
    for (int i = tid; i < BM * EE / 4; i += NTHREADS) {
        int e = i * 4;
        int r = e >> 6, c = e & 63;
        float4 t = *reinterpret_cast<const float4*>(qp + (size_t)r * GR + c);
        t.x = tf32_rna(t.x); t.y = tf32_rna(t.y);
        t.z = tf32_rna(t.z); t.w = tf32_rna(t.w);
        *reinterpret_cast<float4*>(Qsm + r * QS + c) = t;
    }
    __syncthreads();

    // ---- Q fragments into registers (A of m16n8k8, per kstep of 8) ----
    const int qr0 = 16 * w + g;
    float qa[8][4];
#pragma unroll
    for (int ks = 0; ks < 8; ks++) {
        qa[ks][0] = Qsm[ qr0      * QS + 8 * ks + tg    ];
        qa[ks][1] = Qsm[(qr0 + 8) * QS + 8 * ks + tg    ];
        qa[ks][2] = Qsm[ qr0      * QS + 8 * ks + tg + 4];
        qa[ks][3] = Qsm[(qr0 + 8) * QS + 8 * ks + tg + 4];
    }
    __syncthreads();   // Q fully consumed before MPs overwrites it

    float o_acc[8][4];
#pragma unroll
    for (int nt = 0; nt < 8; nt++)
#pragma unroll
        for (int j = 0; j < 4; j++) o_acc[nt][j] = 0.f;

    float m0 = -1e30f, m1 = -1e30f;    // running row max (log2 domain), rows qr0 / qr0+8
    float l0 = 0.f,    l1 = 0.f;       // running row sum (lane-partial over quad)
    const float sc = 0.125f * 1.44269504088896340736f;  // (1/sqrt(E)) * log2(e)

    for (int kt = 0; kt < SK / BN; kt++) {
        const int s0 = kt * BN;

        // ---- stage K, V (tf32) and mask (fp32) ----
        for (int i = tid; i < BN * EE / 4; i += NTHREADS) {
            int e = i * 4; int r = e >> 6, c = e & 63;
            float4 t = *reinterpret_cast<const float4*>(kp + (size_t)(s0 + r) * GR + c);
            t.x = tf32_rna(t.x); t.y = tf32_rna(t.y);
            t.z = tf32_rna(t.z); t.w = tf32_rna(t.w);
            *reinterpret_cast<float4*>(Ksm + r * KSS + c) = t;
        }
        for (int i = tid; i < BN * DD / 4; i += NTHREADS) {
            int e = i * 4; int r = e >> 6, c = e & 63;
            float4 t = *reinterpret_cast<const float4*>(vp + (size_t)(s0 + r) * GR + c);
            t.x = tf32_rna(t.x); t.y = tf32_rna(t.y);
            t.z = tf32_rna(t.z); t.w = tf32_rna(t.w);
            *reinterpret_cast<float4*>(Vsm + r * VSS + c) = t;
        }
        for (int i = tid; i < BM * BN / 4; i += NTHREADS) {
            int e = i * 4; int r = e >> 6, c = e & 63;
            float4 t = *reinterpret_cast<const float4*>(mp + (size_t)r * SK + s0 + c);
            *reinterpret_cast<float4*>(MPs + r * QS + c) = t;
        }
        __syncthreads();

        // ---- S = Q * K^T (per-warp m16 x n64, k = E = 64) ----
        float s_c[8][4];
#pragma unroll
        for (int nt = 0; nt < 8; nt++)
#pragma unroll
            for (int j = 0; j < 4; j++) s_c[nt][j] = 0.f;

#pragma unroll
        for (int ks = 0; ks < 8; ks++) {
#pragma unroll
            for (int nt = 0; nt < 8; nt++) {
                float bb[2];
                const int kr = 8 * nt + g;          // kv row within tile
                bb[0] = Ksm[kr * KSS + 8 * ks + tg    ];
                bb[1] = Ksm[kr * KSS + 8 * ks + tg + 4];
                mma_tf32(s_c[nt], qa[ks], bb);
            }
        }

        // ---- add mask, scale into log2 domain, row max ----
        float rmax0 = -1e30f, rmax1 = -1e30f;
#pragma unroll
        for (int nt = 0; nt < 8; nt++) {
            const int c0 = 8 * nt + 2 * tg;
            float2 mr0 = *reinterpret_cast<const float2*>(MPs +  qr0      * QS + c0);
            float2 mr1 = *reinterpret_cast<const float2*>(MPs + (qr0 + 8) * QS + c0);
            s_c[nt][0] = (s_c[nt][0] + mr0.x) * sc;
            s_c[nt][1] = (s_c[nt][1] + mr0.y) * sc;
            s_c[nt][2] = (s_c[nt][2] + mr1.x) * sc;
            s_c[nt][3] = (s_c[nt][3] + mr1.y) * sc;
            rmax0 = fmaxf(rmax0, fmaxf(s_c[nt][0], s_c[nt][1]));
            rmax1 = fmaxf(rmax1, fmaxf(s_c[nt][2], s_c[nt][3]));
        }
        rmax0 = fmaxf(rmax0, __shfl_xor_sync(0xffffffffu, rmax0, 1));
        rmax0 = fmaxf(rmax0, __shfl_xor_sync(0xffffffffu, rmax0, 2));
        rmax1 = fmaxf(rmax1, __shfl_xor_sync(0xffffffffu, rmax1, 1));
        rmax1 = fmaxf(rmax1, __shfl_xor_sync(0xffffffffu, rmax1, 2));

        const float nm0 = fmaxf(m0, rmax0);
        const float nm1 = fmaxf(m1, rmax1);
        const float al0 = exp2f(m0 - nm0);
        const float al1 = exp2f(m1 - nm1);
        m0 = nm0; m1 = nm1;

        float ps0 = 0.f, ps1 = 0.f;
#pragma unroll
        for (int nt = 0; nt < 8; nt++) {
            const float p0 = exp2f(s_c[nt][0] - m0);
            const float p1 = exp2f(s_c[nt][1] - m0);
            const float p2 = exp2f(s_c[nt][2] - m1);
            const float p3 = exp2f(s_c[nt][3] - m1);
            ps0 += p0 + p1;
            ps1 += p2 + p3;
            const int c0 = 8 * nt + 2 * tg;
            float2 w0; w0.x = tf32_rna(p0); w0.y = tf32_rna(p1);
            float2 w1; w1.x = tf32_rna(p2); w1.y = tf32_rna(p3);
            *reinterpret_cast<float2*>(MPs +  qr0      * QS + c0) = w0;
            *reinterpret_cast<float2*>(MPs + (qr0 + 8) * QS + c0) = w1;
            o_acc[nt][0] *= al0; o_acc[nt][1] *= al0;
            o_acc[nt][2] *= al1; o_acc[nt][3] *= al1;
        }
        l0 = l0 * al0 + ps0;
        l1 = l1 * al1 + ps1;

        __syncwarp();   // P stores visible to whole warp before A-fragment reads

        // ---- O += P * V  (k = BN = 64, n = D = 64) ----
#pragma unroll
        for (int ks = 0; ks < 8; ks++) {
            float pa[4];
            pa[0] = MPs[ qr0      * QS + 8 * ks + tg    ];
            pa[1] = MPs[(qr0 + 8) * QS + 8 * ks + tg    ];
            pa[2] = MPs[ qr0      * QS + 8 * ks + tg + 4];
            pa[3] = MPs[(qr0 + 8) * QS + 8 * ks + tg + 4];
#pragma unroll
            for (int nt = 0; nt < 8; nt++) {
                float bb[2];
                bb[0] = Vsm[(8 * ks + tg    ) * VSS + 8 * nt + g];
                bb[1] = Vsm[(8 * ks + tg + 4) * VSS + 8 * nt + g];
                mma_tf32(o_acc[nt], pa, bb);
            }
        }
        __syncthreads();   // before next iteration's staging overwrites K/V/MP
    }

    // ---- finalize: reduce l over quad, normalize, write out ----
    l0 += __shfl_xor_sync(0xffffffffu, l0, 1);
    l0 += __shfl_xor_sync(0xffffffffu, l0, 2);
    l1 += __shfl_xor_sync(0xffffffffu, l1, 1);
    l1 += __shfl_xor_sync(0xffffffffu, l1, 2);
    const float inv0 = 1.f / l0;
    const float inv1 = 1.f / l1;

#pragma unroll
    for (int nt = 0; nt < 8; nt++) {
        const int c0 = 8 * nt + 2 * tg;
        float2 r0; r0.x = o_acc[nt][0] * inv0; r0.y = o_acc[nt][1] * inv0;
        float2 r1; r1.x = o_acc[nt][2] * inv1; r1.y = o_acc[nt][3] * inv1;
        *reinterpret_cast<float2*>(op + (size_t) qr0      * GR + c0) = r0;
        *reinterpret_cast<float2*>(op + (size_t)(qr0 + 8) * GR + c0) = r1;
    }
}

extern "C" void kernel_launch(void* const* d_in, const int* in_sizes, int n_in,
                              void* d_out, int out_size)
{
    const float* q    = (const float*)d_in[0];
    const float* k    = (const float*)d_in[1];
    const float* v    = (const float*)d_in[2];
    const float* mask = (const float*)d_in[3];
    float* out        = (float*)d_out;

    cudaFuncSetAttribute(attn_kernel,
                         cudaFuncAttributeMaxDynamicSharedMemorySize, SMEM_BYTES);

    dim3 grid(LQ / BM, NH, NB);   // (16, 16, 2)
    attn_kernel<<<grid, NTHREADS, SMEM_BYTES>>>(q, k, v, mask, out);
}

// round 6
// speedup vs baseline: 1.0146x; 1.0146x over previous
#include <cuda_runtime.h>
#include <cstdint>
#include <cstddef>

// Problem constants
#define NB 2
#define LQ 2048
#define SK 2048
#define NH 16
#define EE 64
#define DD 64
#define GR 1024          // row stride in elements for Q/K/V/O: H*E = H*D = 1024

// Tile config
#define BM 128           // q rows per CTA
#define BN 64            // kv rows per tile
#define NT (SK / BN)     // 32 kv tiles
#define NTHREADS 256     // 8 warps, each owns 16 q rows

// SMEM strides (floats). 72 => 288B rows (16B-aligned for cp.async), conflict-free frags.
#define KVS 72
#define PS  68

#define KBUF (BN * KVS)                    // 4608 floats per K buffer
#define VBUF (BN * KVS)                    // 4608 floats per V buffer
#define SMEM_FLOATS (2*KBUF + 2*VBUF + BM*PS)   // 9216+9216+8704 = 27136
#define SMEM_BYTES  (SMEM_FLOATS * 4)           // 108544 B -> 2 CTAs/SM

__device__ __forceinline__ float tf32_rna(float x) {
    uint32_t u;
    asm("cvt.rna.tf32.f32 %0, %1;" : "=r"(u) : "f"(x));
    return __uint_as_float(u);
}

__device__ __forceinline__ float ex2(float x) {
    float y;
    asm("ex2.approx.ftz.f32 %0, %1;" : "=f"(y) : "f"(x));
    return y;
}

__device__ __forceinline__ void cpa16(uint32_t dst, const float* src) {
    asm volatile("cp.async.cg.shared.global [%0], [%1], 16;" :: "r"(dst), "l"(src));
}
__device__ __forceinline__ void cpa_commit() {
    asm volatile("cp.async.commit_group;");
}
template <int N>
__device__ __forceinline__ void cpa_wait() {
    asm volatile("cp.async.wait_group %0;" :: "n"(N));
}

// D += A * B, m16n8k8 tf32, A row-major (m x k), B col (element (k,n))
__device__ __forceinline__ void mma_tf32(float c[4], const float a[4], const float b[2]) {
    asm volatile(
        "mma.sync.aligned.m16n8k8.row.col.f32.tf32.tf32.f32 "
        "{%0,%1,%2,%3}, {%4,%5,%6,%7}, {%8,%9}, {%0,%1,%2,%3};"
        : "+f"(c[0]), "+f"(c[1]), "+f"(c[2]), "+f"(c[3])
        : "r"(__float_as_uint(a[0])), "r"(__float_as_uint(a[1])),
          "r"(__float_as_uint(a[2])), "r"(__float_as_uint(a[3])),
          "r"(__float_as_uint(b[0])), "r"(__float_as_uint(b[1])));
}

__global__ void __launch_bounds__(NTHREADS, 2)
attn_kernel(const float* __restrict__ q,
            const float* __restrict__ k,
            const float* __restrict__ v,
            const float* __restrict__ mask,
            float* __restrict__ out)
{
    extern __shared__ float smem[];
    float* Ksm = smem;                  // [2][BN][KVS]
    float* Vsm = smem + 2 * KBUF;       // [2][BN][KVS]
    float* Psm = Vsm + 2 * VBUF;        // [BM][PS] : Q staging, then P tile
    const uint32_t Ksm_u = (uint32_t)__cvta_generic_to_shared(Ksm);
    const uint32_t Vsm_u = (uint32_t)__cvta_generic_to_shared(Vsm);

    const int tid  = threadIdx.x;
    const int w    = tid >> 5;         // warp 0..7 -> q rows [16w, 16w+16)
    const int lane = tid & 31;
    const int g    = lane >> 2;        // groupID 0..7
    const int tg   = lane & 3;         // thread-in-group 0..3

    const int q0 = blockIdx.x * BM;    // q tile start
    const int h  = blockIdx.y;
    const int b  = blockIdx.z;

    const float* qp = q    + (((size_t)b * LQ + q0) * NH + h) * EE;
    const float* kp = k    + (((size_t)b * SK) * NH + h) * EE;
    const float* vp = v    + (((size_t)b * SK) * NH + h) * DD;
    const float* mp = mask + (size_t)q0 * SK;
    float*       op = out  + (((size_t)b * LQ + q0) * NH + h) * DD;

    // ---- stage Q (fp32 -> tf32, done once) into P region ----
    for (int i = tid; i < BM * EE / 4; i += NTHREADS) {
        int e = i * 4;
        int r = e >> 6, c = e & 63;
        float4 t = *reinterpret_cast<const float4*>(qp + (size_t)r * GR + c);
        t.x = tf32_rna(t.x); t.y = tf32_rna(t.y);
        t.z = tf32_rna(t.z); t.w = tf32_rna(t.w);
        *reinterpret_cast<float4*>(Psm + r * PS + c) = t;
    }
    __syncthreads();

    // ---- Q fragments into registers (A of m16n8k8, per kstep of 8) ----
    const int qr0 = 16 * w + g;
    float qa[8][4];
#pragma unroll
    for (int ks = 0; ks < 8; ks++) {
        qa[ks][0] = Psm[ qr0      * PS + 8 * ks + tg    ];
        qa[ks][1] = Psm[(qr0 + 8) * PS + 8 * ks + tg    ];
        qa[ks][2] = Psm[ qr0      * PS + 8 * ks + tg + 4];
        qa[ks][3] = Psm[(qr0 + 8) * PS + 8 * ks + tg + 4];
    }
    __syncthreads();   // Q fully consumed before Psm is reused for P

    float o_acc[8][4];
#pragma unroll
    for (int nt = 0; nt < 8; nt++)
#pragma unroll
        for (int j = 0; j < 4; j++) o_acc[nt][j] = 0.f;

    float m0 = -1e30f, m1 = -1e30f;    // running row max (log2 domain)
    float l0 = 0.f,    l1 = 0.f;       // running row sum (lane-partial over quad)
    const float sc = 0.125f * 1.44269504088896340736f;  // (1/sqrt(E)) * log2(e)

    // cp.async chunk assignment: 1024 16B-chunks per tile, 4 per thread
    const int cr0 = tid >> 4;               // row within tile for chunk 0
    const int cc  = (tid & 15) * 4;         // col (floats)

    // ---- preload tile 0 ----
    {
        const float* kg = kp;  const float* vg = vp;
#pragma unroll
        for (int t = 0; t < 4; t++) {
            int r = cr0 + t * 16;
            cpa16(Ksm_u + (uint32_t)((r * KVS + cc) * 4), kg + (size_t)r * GR + cc);
            cpa16(Vsm_u + (uint32_t)((r * KVS + cc) * 4), vg + (size_t)r * GR + cc);
        }
        cpa_commit();
    }

    for (int kt = 0; kt < NT; kt++) {
        const int s0 = kt * BN;
        const int buf = kt & 1;

        // ---- issue cp.async for tile kt+1 into the other buffer ----
        if (kt + 1 < NT) {
            const float* kg = kp + (size_t)(s0 + BN) * GR;
            const float* vg = vp + (size_t)(s0 + BN) * GR;
            const uint32_t kb = Ksm_u + (uint32_t)((buf ^ 1) * KBUF * 4);
            const uint32_t vb = Vsm_u + (uint32_t)((buf ^ 1) * VBUF * 4);
#pragma unroll
            for (int t = 0; t < 4; t++) {
                int r = cr0 + t * 16;
                cpa16(kb + (uint32_t)((r * KVS + cc) * 4), kg + (size_t)r * GR + cc);
                cpa16(vb + (uint32_t)((r * KVS + cc) * 4), vg + (size_t)r * GR + cc);
            }
            cpa_commit();
            cpa_wait<1>();
        } else {
            cpa_wait<0>();
        }

        // ---- RNA-convert the arrived tile in place (each thread: its own chunks) ----
        {
            float* kb = Ksm + buf * KBUF;
            float* vb = Vsm + buf * VBUF;
#pragma unroll
            for (int t = 0; t < 4; t++) {
                int r = cr0 + t * 16;
                float4* pk = reinterpret_cast<float4*>(kb + r * KVS + cc);
                float4 xk = *pk;
                xk.x = tf32_rna(xk.x); xk.y = tf32_rna(xk.y);
                xk.z = tf32_rna(xk.z); xk.w = tf32_rna(xk.w);
                *pk = xk;
                float4* pv = reinterpret_cast<float4*>(vb + r * KVS + cc);
                float4 xv = *pv;
                xv.x = tf32_rna(xv.x); xv.y = tf32_rna(xv.y);
                xv.z = tf32_rna(xv.z); xv.w = tf32_rna(xv.w);
                *pv = xv;
            }
        }
        __syncthreads();

        const float* Kb = Ksm + buf * KBUF;
        const float* Vb = Vsm + buf * VBUF;

        // ---- S = Q * K^T (per-warp m16 x n64, k = E = 64) ----
        float s_c[8][4];
#pragma unroll
        for (int nt = 0; nt < 8; nt++)
#pragma unroll
            for (int j = 0; j < 4; j++) s_c[nt][j] = 0.f;

#pragma unroll
        for (int ks = 0; ks < 8; ks++) {
#pragma unroll
            for (int nt = 0; nt < 8; nt++) {
                float bb[2];
                const int kr = 8 * nt + g;          // kv row within tile
                bb[0] = Kb[kr * KVS + 8 * ks + tg    ];
                bb[1] = Kb[kr * KVS + 8 * ks + tg + 4];
                mma_tf32(s_c[nt], qa[ks], bb);
            }
        }

        // ---- add mask (direct from global, L2-resident), scale, row max ----
        const float* mr0p = mp + (size_t)qr0 * SK + s0;
        const float* mr1p = mr0p + (size_t)8 * SK;
        float rmax0 = -1e30f, rmax1 = -1e30f;
#pragma unroll
        for (int nt = 0; nt < 8; nt++) {
            const int c0 = 8 * nt + 2 * tg;
            float2 mr0 = __ldg(reinterpret_cast<const float2*>(mr0p + c0));
            float2 mr1 = __ldg(reinterpret_cast<const float2*>(mr1p + c0));
            s_c[nt][0] = (s_c[nt][0] + mr0.x) * sc;
            s_c[nt][1] = (s_c[nt][1] + mr0.y) * sc;
            s_c[nt][2] = (s_c[nt][2] + mr1.x) * sc;
            s_c[nt][3] = (s_c[nt][3] + mr1.y) * sc;
            rmax0 = fmaxf(rmax0, fmaxf(s_c[nt][0], s_c[nt][1]));
            rmax1 = fmaxf(rmax1, fmaxf(s_c[nt][2], s_c[nt][3]));
        }
        rmax0 = fmaxf(rmax0, __shfl_xor_sync(0xffffffffu, rmax0, 1));
        rmax0 = fmaxf(rmax0, __shfl_xor_sync(0xffffffffu, rmax0, 2));
        rmax1 = fmaxf(rmax1, __shfl_xor_sync(0xffffffffu, rmax1, 1));
        rmax1 = fmaxf(rmax1, __shfl_xor_sync(0xffffffffu, rmax1, 2));

        const float nm0 = fmaxf(m0, rmax0);
        const float nm1 = fmaxf(m1, rmax1);
        const float al0 = ex2(m0 - nm0);
        const float al1 = ex2(m1 - nm1);
        m0 = nm0; m1 = nm1;

        float ps0 = 0.f, ps1 = 0.f;
#pragma unroll
        for (int nt = 0; nt < 8; nt++) {
            const float p0 = ex2(s_c[nt][0] - m0);
            const float p1 = ex2(s_c[nt][1] - m0);
            const float p2 = ex2(s_c[nt][2] - m1);
            const float p3 = ex2(s_c[nt][3] - m1);
            ps0 += p0 + p1;
            ps1 += p2 + p3;
            const int c0 = 8 * nt + 2 * tg;
            float2 w0; w0.x = tf32_rna(p0); w0.y = tf32_rna(p1);
            float2 w1; w1.x = tf32_rna(p2); w1.y = tf32_rna(p3);
            *reinterpret_cast<float2*>(Psm +  qr0      * PS + c0) = w0;
            *reinterpret_cast<float2*>(Psm + (qr0 + 8) * PS + c0) = w1;
            o_acc[nt][0] *= al0; o_acc[nt][1] *= al0;
            o_acc[nt][2] *= al1; o_acc[nt][3] *= al1;
        }
        l0 = l0 * al0 + ps0;
        l1 = l1 * al1 + ps1;

        __syncwarp();   // P stores visible to whole warp before A-fragment reads

        // ---- O += P * V  (k = BN = 64, n = D = 64) ----
#pragma unroll
        for (int ks = 0; ks < 8; ks++) {
            float pa[4];
            pa[0] = Psm[ qr0      * PS + 8 * ks + tg    ];
            pa[1] = Psm[(qr0 + 8) * PS + 8 * ks + tg    ];
            pa[2] = Psm[ qr0      * PS + 8 * ks + tg + 4];
            pa[3] = Psm[(qr0 + 8) * PS + 8 * ks + tg + 4];
#pragma unroll
            for (int nt = 0; nt < 8; nt++) {
                float bb[2];
                bb[0] = Vb[(8 * ks + tg    ) * KVS + 8 * nt + g];
                bb[1] = Vb[(8 * ks + tg + 4) * KVS + 8 * nt + g];
                mma_tf32(o_acc[nt], pa, bb);
            }
        }
        __syncthreads();   // all warps done with buf before next iter overwrites buf^1
    }

    // ---- finalize: reduce l over quad, normalize, write out ----
    l0 += __shfl_xor_sync(0xffffffffu, l0, 1);
    l0 += __shfl_xor_sync(0xffffffffu, l0, 2);
    l1 += __shfl_xor_sync(0xffffffffu, l1, 1);
    l1 += __shfl_xor_sync(0xffffffffu, l1, 2);
    const float inv0 = 1.f / l0;
    const float inv1 = 1.f / l1;

#pragma unroll
    for (int nt = 0; nt < 8; nt++) {
        const int c0 = 8 * nt + 2 * tg;
        float2 r0; r0.x = o_acc[nt][0] * inv0; r0.y = o_acc[nt][1] * inv0;
        float2 r1; r1.x = o_acc[nt][2] * inv1; r1.y = o_acc[nt][3] * inv1;
        *reinterpret_cast<float2*>(op + (size_t) qr0      * GR + c0) = r0;
        *reinterpret_cast<float2*>(op + (size_t)(qr0 + 8) * GR + c0) = r1;
    }
}

extern "C" void kernel_launch(void* const* d_in, const int* in_sizes, int n_in,
                              void* d_out, int out_size)
{
    const float* q    = (const float*)d_in[0];
    const float* k    = (const float*)d_in[1];
    const float* v    = (const float*)d_in[2];
    const float* mask = (const float*)d_in[3];
    float* out        = (float*)d_out;

    cudaFuncSetAttribute(attn_kernel,
                         cudaFuncAttributeMaxDynamicSharedMemorySize, SMEM_BYTES);

    dim3 grid(LQ / BM, NH, NB);   // (16, 16, 2)
    attn_kernel<<<grid, NTHREADS, SMEM_BYTES>>>(q, k, v, mask, out);
}

// round 7
// speedup vs baseline: 1.1397x; 1.1233x over previous
#include <cuda_runtime.h>
#include <cstdint>
#include <cstddef>

// Problem constants
#define NB 2
#define LQ 2048
#define SK 2048
#define NH 16
#define EE 64
#define DD 64
#define GR 1024          // row stride in elements for Q/K/V/O: H*E = H*D = 1024

// Tile config
#define BM 128           // q rows per CTA
#define BN 64            // kv rows per tile
#define NT (SK / BN)     // 32 kv tiles
#define NTHREADS 256     // 8 warps, each owns 16 q rows

// SMEM strides (floats), all multiples of 4 (16B cp.async alignment).
// KSS=68: K B-frag bank = 4g+tg -> all 32 banks distinct (conflict-free)
// VSS=72: V B-frag bank = 8tg+g -> all 32 banks distinct (conflict-free)
// PS =68: P A-frag bank = 4g+tg -> conflict-free
#define KSS 68
#define VSS 72
#define PS  68

#define KBUF (BN * KSS)                    // 4352 floats per K buffer
#define VBUF (BN * VSS)                    // 4608 floats per V buffer
#define SMEM_FLOATS (2*KBUF + 2*VBUF + BM*PS)   // 8704+9216+8704 = 26624
#define SMEM_BYTES  (SMEM_FLOATS * 4)           // 106496 B -> 2 CTAs/SM

__device__ __forceinline__ float tf32_rna(float x) {
    uint32_t u;
    asm("cvt.rna.tf32.f32 %0, %1;" : "=r"(u) : "f"(x));
    return __uint_as_float(u);
}

__device__ __forceinline__ float ex2(float x) {
    float y;
    asm("ex2.approx.ftz.f32 %0, %1;" : "=f"(y) : "f"(x));
    return y;
}

__device__ __forceinline__ void cpa16(uint32_t dst, const float* src) {
    asm volatile("cp.async.cg.shared.global [%0], [%1], 16;" :: "r"(dst), "l"(src));
}
__device__ __forceinline__ void cpa_commit() {
    asm volatile("cp.async.commit_group;");
}
template <int N>
__device__ __forceinline__ void cpa_wait() {
    asm volatile("cp.async.wait_group %0;" :: "n"(N));
}

// D += A * B, m16n8k8 tf32, A row-major (m x k), B col (element (k,n))
__device__ __forceinline__ void mma_tf32(float c[4], const float a[4], const float b[2]) {
    asm volatile(
        "mma.sync.aligned.m16n8k8.row.col.f32.tf32.tf32.f32 "
        "{%0,%1,%2,%3}, {%4,%5,%6,%7}, {%8,%9}, {%0,%1,%2,%3};"
        : "+f"(c[0]), "+f"(c[1]), "+f"(c[2]), "+f"(c[3])
        : "r"(__float_as_uint(a[0])), "r"(__float_as_uint(a[1])),
          "r"(__float_as_uint(a[2])), "r"(__float_as_uint(a[3])),
          "r"(__float_as_uint(b[0])), "r"(__float_as_uint(b[1])));
}

__global__ void __launch_bounds__(NTHREADS, 2)
attn_kernel(const float* __restrict__ q,
            const float* __restrict__ k,
            const float* __restrict__ v,
            const float* __restrict__ mask,
            float* __restrict__ out)
{
    extern __shared__ float smem[];
    float* Ksm = smem;                  // [2][BN][KSS]
    float* Vsm = smem + 2 * KBUF;       // [2][BN][VSS]
    float* Psm = Vsm + 2 * VBUF;        // [BM][PS] : Q staging, then P tile
    const uint32_t Ksm_u = (uint32_t)__cvta_generic_to_shared(Ksm);
    const uint32_t Vsm_u = (uint32_t)__cvta_generic_to_shared(Vsm);

    const int tid  = threadIdx.x;
    const int w    = tid >> 5;         // warp 0..7 -> q rows [16w, 16w+16)
    const int lane = tid & 31;
    const int g    = lane >> 2;        // groupID 0..7
    const int tg   = lane & 3;         // thread-in-group 0..3

    const int q0 = blockIdx.x * BM;    // q tile start
    const int h  = blockIdx.y;
    const int b  = blockIdx.z;

    const float* qp = q    + (((size_t)b * LQ + q0) * NH + h) * EE;
    const float* kp = k    + (((size_t)b * SK) * NH + h) * EE;
    const float* vp = v    + (((size_t)b * SK) * NH + h) * DD;
    const float* mp = mask + (size_t)q0 * SK;
    float*       op = out  + (((size_t)b * LQ + q0) * NH + h) * DD;

    // ---- stage Q (fp32 -> tf32, done once) into P region ----
    for (int i = tid; i < BM * EE / 4; i += NTHREADS) {
        int e = i * 4;
        int r = e >> 6, c = e & 63;
        float4 t = *reinterpret_cast<const float4*>(qp + (size_t)r * GR + c);
        t.x = tf32_rna(t.x); t.y = tf32_rna(t.y);
        t.z = tf32_rna(t.z); t.w = tf32_rna(t.w);
        *reinterpret_cast<float4*>(Psm + r * PS + c) = t;
    }
    __syncthreads();

    // ---- Q fragments into registers (A of m16n8k8, per kstep of 8) ----
    const int qr0 = 16 * w + g;
    float qa[8][4];
#pragma unroll
    for (int ks = 0; ks < 8; ks++) {
        qa[ks][0] = Psm[ qr0      * PS + 8 * ks + tg    ];
        qa[ks][1] = Psm[(qr0 + 8) * PS + 8 * ks + tg    ];
        qa[ks][2] = Psm[ qr0      * PS + 8 * ks + tg + 4];
        qa[ks][3] = Psm[(qr0 + 8) * PS + 8 * ks + tg + 4];
    }
    __syncthreads();   // Q fully consumed before Psm is reused for P

    float o_acc[8][4];
#pragma unroll
    for (int nt = 0; nt < 8; nt++)
#pragma unroll
        for (int j = 0; j < 4; j++) o_acc[nt][j] = 0.f;

    float m0 = -1e30f, m1 = -1e30f;    // running row max (log2 domain)
    float l0 = 0.f,    l1 = 0.f;       // running row sum (lane-partial over quad)
    const float sc = 0.125f * 1.44269504088896340736f;  // (1/sqrt(E)) * log2(e)

    // cp.async chunk assignment: 1024 16B-chunks per tile, 4 per thread
    const int cr0 = tid >> 4;               // row within tile for chunk 0
    const int cc  = (tid & 15) * 4;         // col (floats)

    // ---- preload tile 0 ----
    {
#pragma unroll
        for (int t = 0; t < 4; t++) {
            int r = cr0 + t * 16;
            cpa16(Ksm_u + (uint32_t)((r * KSS + cc) * 4), kp + (size_t)r * GR + cc);
            cpa16(Vsm_u + (uint32_t)((r * VSS + cc) * 4), vp + (size_t)r * GR + cc);
        }
        cpa_commit();
    }

    for (int kt = 0; kt < NT; kt++) {
        const int s0 = kt * BN;
        const int buf = kt & 1;

        // ---- issue cp.async for tile kt+1 into the other buffer ----
        if (kt + 1 < NT) {
            const float* kg = kp + (size_t)(s0 + BN) * GR;
            const float* vg = vp + (size_t)(s0 + BN) * GR;
            const uint32_t kb = Ksm_u + (uint32_t)((buf ^ 1) * KBUF * 4);
            const uint32_t vb = Vsm_u + (uint32_t)((buf ^ 1) * VBUF * 4);
#pragma unroll
            for (int t = 0; t < 4; t++) {
                int r = cr0 + t * 16;
                cpa16(kb + (uint32_t)((r * KSS + cc) * 4), kg + (size_t)r * GR + cc);
                cpa16(vb + (uint32_t)((r * VSS + cc) * 4), vg + (size_t)r * GR + cc);
            }
            cpa_commit();
            cpa_wait<1>();
        } else {
            cpa_wait<0>();
        }

        // ---- RNA-convert the arrived tile in place (each thread: its own chunks) ----
        {
            float* kb = Ksm + buf * KBUF;
            float* vb = Vsm + buf * VBUF;
#pragma unroll
            for (int t = 0; t < 4; t++) {
                int r = cr0 + t * 16;
                float4* pk = reinterpret_cast<float4*>(kb + r * KSS + cc);
                float4 xk = *pk;
                xk.x = tf32_rna(xk.x); xk.y = tf32_rna(xk.y);
                xk.z = tf32_rna(xk.z); xk.w = tf32_rna(xk.w);
                *pk = xk;
                float4* pv = reinterpret_cast<float4*>(vb + r * VSS + cc);
                float4 xv = *pv;
                xv.x = tf32_rna(xv.x); xv.y = tf32_rna(xv.y);
                xv.z = tf32_rna(xv.z); xv.w = tf32_rna(xv.w);
                *pv = xv;
            }
        }
        __syncthreads();

        const float* Kb = Ksm + buf * KBUF;
        const float* Vb = Vsm + buf * VBUF;

        // ---- S = Q * K^T (per-warp m16 x n64, k = E = 64) ----
        float s_c[8][4];
#pragma unroll
        for (int nt = 0; nt < 8; nt++)
#pragma unroll
            for (int j = 0; j < 4; j++) s_c[nt][j] = 0.f;

#pragma unroll
        for (int ks = 0; ks < 8; ks++) {
#pragma unroll
            for (int nt = 0; nt < 8; nt++) {
                float bb[2];
                const int kr = 8 * nt + g;          // kv row within tile
                bb[0] = Kb[kr * KSS + 8 * ks + tg    ];
                bb[1] = Kb[kr * KSS + 8 * ks + tg + 4];
                mma_tf32(s_c[nt], qa[ks], bb);
            }
        }

        // ---- add mask (direct from global, L2-resident), scale, row max ----
        const float* mr0p = mp + (size_t)qr0 * SK + s0;
        const float* mr1p = mr0p + (size_t)8 * SK;
        float rmax0 = -1e30f, rmax1 = -1e30f;
#pragma unroll
        for (int nt = 0; nt < 8; nt++) {
            const int c0 = 8 * nt + 2 * tg;
            float2 mr0 = __ldg(reinterpret_cast<const float2*>(mr0p + c0));
            float2 mr1 = __ldg(reinterpret_cast<const float2*>(mr1p + c0));
            s_c[nt][0] = (s_c[nt][0] + mr0.x) * sc;
            s_c[nt][1] = (s_c[nt][1] + mr0.y) * sc;
            s_c[nt][2] = (s_c[nt][2] + mr1.x) * sc;
            s_c[nt][3] = (s_c[nt][3] + mr1.y) * sc;
            rmax0 = fmaxf(rmax0, fmaxf(s_c[nt][0], s_c[nt][1]));
            rmax1 = fmaxf(rmax1, fmaxf(s_c[nt][2], s_c[nt][3]));
        }
        rmax0 = fmaxf(rmax0, __shfl_xor_sync(0xffffffffu, rmax0, 1));
        rmax0 = fmaxf(rmax0, __shfl_xor_sync(0xffffffffu, rmax0, 2));
        rmax1 = fmaxf(rmax1, __shfl_xor_sync(0xffffffffu, rmax1, 1));
        rmax1 = fmaxf(rmax1, __shfl_xor_sync(0xffffffffu, rmax1, 2));

        const float nm0 = fmaxf(m0, rmax0);
        const float nm1 = fmaxf(m1, rmax1);
        const float al0 = ex2(m0 - nm0);
        const float al1 = ex2(m1 - nm1);
        m0 = nm0; m1 = nm1;

        float ps0 = 0.f, ps1 = 0.f;
#pragma unroll
        for (int nt = 0; nt < 8; nt++) {
            const float p0 = ex2(s_c[nt][0] - m0);
            const float p1 = ex2(s_c[nt][1] - m0);
            const float p2 = ex2(s_c[nt][2] - m1);
            const float p3 = ex2(s_c[nt][3] - m1);
            ps0 += p0 + p1;
            ps1 += p2 + p3;
            const int c0 = 8 * nt + 2 * tg;
            float2 w0; w0.x = tf32_rna(p0); w0.y = tf32_rna(p1);
            float2 w1; w1.x = tf32_rna(p2); w1.y = tf32_rna(p3);
            *reinterpret_cast<float2*>(Psm +  qr0      * PS + c0) = w0;
            *reinterpret_cast<float2*>(Psm + (qr0 + 8) * PS + c0) = w1;
            o_acc[nt][0] *= al0; o_acc[nt][1] *= al0;
            o_acc[nt][2] *= al1; o_acc[nt][3] *= al1;
        }
        l0 = l0 * al0 + ps0;
        l1 = l1 * al1 + ps1;

        __syncwarp();   // P stores visible to whole warp before A-fragment reads

        // ---- O += P * V  (k = BN = 64, n = D = 64) ----
#pragma unroll
        for (int ks = 0; ks < 8; ks++) {
            float pa[4];
            pa[0] = Psm[ qr0      * PS + 8 * ks + tg    ];
            pa[1] = Psm[(qr0 + 8) * PS + 8 * ks + tg    ];
            pa[2] = Psm[ qr0      * PS + 8 * ks + tg + 4];
            pa[3] = Psm[(qr0 + 8) * PS + 8 * ks + tg + 4];
#pragma unroll
            for (int nt = 0; nt < 8; nt++) {
                float bb[2];
                bb[0] = Vb[(8 * ks + tg    ) * VSS + 8 * nt + g];
                bb[1] = Vb[(8 * ks + tg + 4) * VSS + 8 * nt + g];
                mma_tf32(o_acc[nt], pa, bb);
            }
        }
        __syncthreads();   // all warps done with buf before next iter overwrites it
    }

    // ---- finalize: reduce l over quad, normalize, write out ----
    l0 += __shfl_xor_sync(0xffffffffu, l0, 1);
    l0 += __shfl_xor_sync(0xffffffffu, l0, 2);
    l1 += __shfl_xor_sync(0xffffffffu, l1, 1);
    l1 += __shfl_xor_sync(0xffffffffu, l1, 2);
    const float inv0 = 1.f / l0;
    const float inv1 = 1.f / l1;

#pragma unroll
    for (int nt = 0; nt < 8; nt++) {
        const int c0 = 8 * nt + 2 * tg;
        float2 r0; r0.x = o_acc[nt][0] * inv0; r0.y = o_acc[nt][1] * inv0;
        float2 r1; r1.x = o_acc[nt][2] * inv1; r1.y = o_acc[nt][3] * inv1;
        *reinterpret_cast<float2*>(op + (size_t) qr0      * GR + c0) = r0;
        *reinterpret_cast<float2*>(op + (size_t)(qr0 + 8) * GR + c0) = r1;
    }
}

extern "C" void kernel_launch(void* const* d_in, const int* in_sizes, int n_in,
                              void* d_out, int out_size)
{
    const float* q    = (const float*)d_in[0];
    const float* k    = (const float*)d_in[1];
    const float* v    = (const float*)d_in[2];
    const float* mask = (const float*)d_in[3];
    float* out        = (float*)d_out;

    cudaFuncSetAttribute(attn_kernel,
                         cudaFuncAttributeMaxDynamicSharedMemorySize, SMEM_BYTES);

    dim3 grid(LQ / BM, NH, NB);   // (16, 16, 2)
    attn_kernel<<<grid, NTHREADS, SMEM_BYTES>>>(q, k, v, mask, out);
}